// round 9
// baseline (speedup 1.0000x reference)
#include <cuda_runtime.h>

#define TPB    256
#define KDIM   4096
#define KD4    1024
#define ND4    1024
#define RANK   8
#define TROWS  8                 // rows per tile
#define NCTA   296               // 2 CTAs x 148 SMs, exactly one wave
#define NTILES 2048              // 16384 / TROWS

typedef unsigned long long u64;

// Interleaved pack of B for perfectly-coalesced LDG.128 (verified R7/R8):
// for 32-wide p-block b, 8 segments of 64 u64; seg sub (= rp*2+pr) holds at
// lane*2+j the pair {B[k][2rp],B[k][2rp+1]} for k = 4*(b*32+lane)+2*pr+j.
__device__ u64 BX_g[4 * KDIM];   // 128 KB

__global__ void pack_BX_kernel(const float* __restrict__ B)
{
    const int o = blockIdx.x * blockDim.x + threadIdx.x;  // 0..16383
    const int b    = o >> 9;
    const int r    = o & 511;
    const int sub  = r >> 6;
    const int lane = (r & 63) >> 1;
    const int j    = r & 1;
    const int rp   = sub >> 1;
    const int pr   = sub & 1;
    const int k    = 4 * (b * 32 + lane) + 2 * pr + j;
    BX_g[o] = ((const u64*)B)[k * 4 + rp];
}

__device__ __forceinline__ u64 pack2(float lo, float hi) {
    u64 d; asm("mov.b64 %0, {%1,%2};" : "=l"(d) : "f"(lo), "f"(hi)); return d;
}
__device__ __forceinline__ void fma2(u64 &d, u64 a, u64 b) {
    asm("fma.rn.f32x2 %0, %1, %2, %0;" : "+l"(d) : "l"(a), "l"(b));
}
__device__ __forceinline__ u64 add2(u64 a, u64 b) {
    u64 d; asm("add.rn.f32x2 %0, %1, %2;" : "=l"(d) : "l"(a), "l"(b)); return d;
}
__device__ __forceinline__ float2 unpack2(u64 v) {
    float2 f; asm("mov.b64 {%0,%1}, %2;" : "=f"(f.x), "=f"(f.y) : "l"(v)); return f;
}

// Warp-specialized pipeline: warps 0-3 produce t for tile s while warps 4-7
// consume t of tile s-1 -> HBM sees continuous mixed read+write streams.
__global__ __launch_bounds__(TPB, 2)
void lora_pipe_kernel(const float* __restrict__ x,
                      const float* __restrict__ A,
                      float* __restrict__ out)
{
    __shared__ u64 part_s[2][TROWS][4];      // [kh][row][rp]
    __shared__ u64 t2buf[2][TROWS][RANK];    // {t,t} pairs, double-buffered

    const int tid  = threadIdx.x;
    const int lane = tid & 31;
    const int warp = tid >> 5;
    const int bid  = blockIdx.x;

    const float4* __restrict__ x4 = (const float4*)x;
    const float4* __restrict__ A4 = (const float4*)A;
    float4* __restrict__ out4 = (float4*)out;

    const bool is_prod = (warp < 4);
    const int  kh = warp & 1;                // producer: k half
    const int  rh = (warp >> 1) & 1;         // producer: row half (4 rows)
    const int  ctid = tid & 127;             // consumer thread id 0..127

    for (int s = 0; s < 8; ++s) {
        // ---------------- producers: compute t for tile tp ----------------
        if (is_prod) {
            const int tp = bid + s * NCTA;
            const bool active = (s <= 6) && (tp < NTILES);
            if (active) {
                const float4* __restrict__ xr =
                    x4 + ((size_t)tp * TROWS + rh * 4) * KD4;

                u64 acc[4][4];
                #pragma unroll
                for (int m = 0; m < 4; ++m)
                    #pragma unroll
                    for (int rp = 0; rp < 4; ++rp) acc[m][rp] = 0ull;

                #pragma unroll 1
                for (int i = 0; i < 16; ++i) {
                    const int p = kh * 512 + i * 32 + lane;   // float4-k index
                    const int b = kh * 16 + i;                // 32-p block

                    const ulonglong2* __restrict__ bx =
                        (const ulonglong2*)BX_g + (size_t)b * 256 + lane;
                    ulonglong2 bp[8];
                    #pragma unroll
                    for (int sub = 0; sub < 8; ++sub)
                        bp[sub] = bx[sub * 32];

                    float4 xv[4];
                    #pragma unroll
                    for (int q = 0; q < 4; ++q)
                        xv[q] = __ldcs(xr + q * KD4 + p);

                    #pragma unroll
                    for (int q = 0; q < 4; ++q) {
                        const u64 xb0 = pack2(xv[q].x, xv[q].x);
                        const u64 xb1 = pack2(xv[q].y, xv[q].y);
                        const u64 xb2 = pack2(xv[q].z, xv[q].z);
                        const u64 xb3 = pack2(xv[q].w, xv[q].w);
                        #pragma unroll
                        for (int rp = 0; rp < 4; ++rp) {
                            fma2(acc[q][rp], xb0, bp[2 * rp].x);
                            fma2(acc[q][rp], xb1, bp[2 * rp].y);
                            fma2(acc[q][rp], xb2, bp[2 * rp + 1].x);
                            fma2(acc[q][rp], xb3, bp[2 * rp + 1].y);
                        }
                    }
                }

                #pragma unroll
                for (int sh = 16; sh; sh >>= 1) {
                    #pragma unroll
                    for (int m = 0; m < 4; ++m)
                        #pragma unroll
                        for (int rp = 0; rp < 4; ++rp)
                            acc[m][rp] = add2(acc[m][rp],
                                __shfl_xor_sync(0xFFFFFFFFu, acc[m][rp], sh));
                }
                if (lane == 0) {
                    #pragma unroll
                    for (int m = 0; m < 4; ++m)
                        #pragma unroll
                        for (int rp = 0; rp < 4; ++rp)
                            part_s[kh][rh * 4 + m][rp] = acc[m][rp];
                }
            }
            // producer-group barrier (all 128 producer threads, always)
            asm volatile("bar.sync 1, 128;" ::: "memory");
            if (active && tid < 32) {
                const int row = tid >> 2;
                const int rp  = tid & 3;
                const u64 sum = add2(part_s[0][row][rp], part_s[1][row][rp]);
                const float2 f = unpack2(sum);
                const float tA = 2.0f * f.x;      // fold SCALING
                const float tB = 2.0f * f.y;
                t2buf[s & 1][row][2 * rp + 0] = pack2(tA, tA);
                t2buf[s & 1][row][2 * rp + 1] = pack2(tB, tB);
            }
        }
        // ---------------- consumers: write out for tile tc ----------------
        else {
            const int tc = bid + (s - 1) * NCTA;
            const bool active = (s >= 1) && (tc < NTILES);
            if (active) {
                const int rb = (s - 1) & 1;
                const size_t row0 = (size_t)tc * TROWS;

                #pragma unroll 1
                for (int c = 0; c < 8; ++c) {
                    const int p = ctid + c * 128;      // out f4 column
                    u64 alo[RANK], ahi[RANK];
                    #pragma unroll
                    for (int r = 0; r < RANK; ++r) {
                        const float4 a = A4[r * ND4 + p];
                        alo[r] = pack2(a.x, a.y);
                        ahi[r] = pack2(a.z, a.w);
                    }
                    #pragma unroll
                    for (int m = 0; m < TROWS; ++m) {
                        const ulonglong2* __restrict__ tp2 =
                            (const ulonglong2*)t2buf[rb][m];
                        const ulonglong2 t01 = tp2[0];
                        const ulonglong2 t23 = tp2[1];
                        const ulonglong2 t45 = tp2[2];
                        const ulonglong2 t67 = tp2[3];

                        u64 olo = 0ull, ohi = 0ull;
                        fma2(olo, t01.x, alo[0]);  fma2(ohi, t01.x, ahi[0]);
                        fma2(olo, t01.y, alo[1]);  fma2(ohi, t01.y, ahi[1]);
                        fma2(olo, t23.x, alo[2]);  fma2(ohi, t23.x, ahi[2]);
                        fma2(olo, t23.y, alo[3]);  fma2(ohi, t23.y, ahi[3]);
                        fma2(olo, t45.x, alo[4]);  fma2(ohi, t45.x, ahi[4]);
                        fma2(olo, t45.y, alo[5]);  fma2(ohi, t45.y, ahi[5]);
                        fma2(olo, t67.x, alo[6]);  fma2(ohi, t67.x, ahi[6]);
                        fma2(olo, t67.y, alo[7]);  fma2(ohi, t67.y, ahi[7]);

                        const float2 f0 = unpack2(olo);
                        const float2 f1 = unpack2(ohi);
                        __stcs(&out4[(row0 + m) * ND4 + p],
                               make_float4(f0.x, f0.y, f1.x, f1.y));
                    }
                }
            }
        }
        __syncthreads();   // step boundary: t2buf[s&1] now valid for step s+1
    }
}

extern "C" void kernel_launch(void* const* d_in, const int* in_sizes, int n_in,
                              void* d_out, int out_size)
{
    const float* x = (const float*)d_in[0];   // [4,4096,4096]
    const float* A = (const float*)d_in[1];   // [8,4096]
    const float* B = (const float*)d_in[2];   // [4096,8]
    float* out = (float*)d_out;               // [4,4096,4096] fp32

    pack_BX_kernel<<<(4 * KDIM) / TPB, TPB>>>(B);
    lora_pipe_kernel<<<NCTA, TPB>>>(x, A, out);
}

// round 10
// speedup vs baseline: 1.0323x; 1.0323x over previous
#include <cuda_runtime.h>
#include <cstdint>

#define TPB    256
#define KDIM   4096
#define KD4    1024
#define ND4    1024
#define RANK   8
#define ROWS   16              // rows per CTA
#define CH     128             // float4 k-chunk per stage
#define NSTG   8               // KD4 / CH

typedef unsigned long long u64;

// Interleaved pack of B for 4-line coalesced LDG.128 (verified R7/R8):
// for 32-wide p-block b, 8 segments of 64 u64; seg sub (= rp*2+pr) holds at
// lane*2+j the pair {B[k][2rp],B[k][2rp+1]} for k = 4*(b*32+lane)+2*pr+j.
__device__ u64 BX_g[4 * KDIM];   // 128 KB, L1/L2 resident

__global__ void pack_BX_kernel(const float* __restrict__ B)
{
    const int o = blockIdx.x * blockDim.x + threadIdx.x;  // 0..16383
    const int b    = o >> 9;
    const int r    = o & 511;
    const int sub  = r >> 6;
    const int lane = (r & 63) >> 1;
    const int j    = r & 1;
    const int rp   = sub >> 1;
    const int pr   = sub & 1;
    const int k    = 4 * (b * 32 + lane) + 2 * pr + j;
    BX_g[o] = ((const u64*)B)[k * 4 + rp];
}

__device__ __forceinline__ u64 pack2(float lo, float hi) {
    u64 d; asm("mov.b64 %0, {%1,%2};" : "=l"(d) : "f"(lo), "f"(hi)); return d;
}
__device__ __forceinline__ void fma2(u64 &d, u64 a, u64 b) {
    asm("fma.rn.f32x2 %0, %1, %2, %0;" : "+l"(d) : "l"(a), "l"(b));
}
__device__ __forceinline__ u64 add2(u64 a, u64 b) {
    u64 d; asm("add.rn.f32x2 %0, %1, %2;" : "=l"(d) : "l"(a), "l"(b)); return d;
}
__device__ __forceinline__ float2 unpack2(u64 v) {
    float2 f; asm("mov.b64 {%0,%1}, %2;" : "=f"(f.x), "=f"(f.y) : "l"(v)); return f;
}

// Fused, with x staged via cp.async.cg double buffer.
// Phase 1: warp = 8 rows (rg) x 32-f4 k-quarter (kq) of each staged chunk.
__global__ __launch_bounds__(TPB, 2)
void lora_v10_kernel(const float* __restrict__ x,
                     const float* __restrict__ A,
                     float* __restrict__ out)
{
    extern __shared__ float4 xs[];          // [2][ROWS][CH] = 64 KB
    __shared__ u64 part_s[4][ROWS][4];      // [kq][row][rp]
    __shared__ u64 t2_s[ROWS][RANK];        // {t,t} broadcast pairs

    const int tid  = threadIdx.x;
    const int lane = tid & 31;
    const int warp = tid >> 5;
    const int kq   = warp >> 1;             // k-quarter of chunk (0..3)
    const int rg   = warp & 1;              // row half (8 rows)
    const size_t row0 = (size_t)blockIdx.x * ROWS;

    const float4* __restrict__ x4 = (const float4*)x + row0 * KD4;
    const float4* __restrict__ A4 = (const float4*)A;
    float4* __restrict__ out4 = (float4*)out;

    const uint32_t xs_base = (uint32_t)__cvta_generic_to_shared(xs);

    // -------- async issue of stage s into buffer buf --------
    auto issue = [&](int s, int buf) {
        #pragma unroll
        for (int t = 0; t < 8; ++t) {
            const int idx = tid + t * TPB;          // 0..2047
            const int r = idx >> 7;                 // row 0..15
            const int c = idx & 127;                // f4 col in chunk
            const float4* src = x4 + (size_t)r * KD4 + s * CH + c;
            const uint32_t dst = xs_base + ((buf * ROWS + r) * CH + c) * 16u;
            asm volatile("cp.async.cg.shared.global [%0], [%1], 16;"
                         :: "r"(dst), "l"(src));
        }
        asm volatile("cp.async.commit_group;" ::: "memory");
    };

    issue(0, 0);
    issue(1, 1);

    u64 acc[8][4];
    #pragma unroll
    for (int m = 0; m < 8; ++m)
        #pragma unroll
        for (int rp = 0; rp < 4; ++rp) acc[m][rp] = 0ull;

    #pragma unroll 1
    for (int s = 0; s < NSTG; ++s) {
        asm volatile("cp.async.wait_group 1;" ::: "memory");
        __syncthreads();                     // stage s visible to all

        const int buf = s & 1;
        const int b = s * 4 + kq;            // global 32-f4 block index

        // B pairs: 8 coalesced LDG.128 (L1-resident BX)
        const ulonglong2* __restrict__ bx =
            (const ulonglong2*)BX_g + (size_t)b * 256 + lane;
        ulonglong2 bp[8];
        #pragma unroll
        for (int sub = 0; sub < 8; ++sub)
            bp[sub] = bx[sub * 32];

        const float4* __restrict__ xb =
            &xs[(buf * ROWS + rg * 8) * CH + kq * 32 + lane];

        #pragma unroll
        for (int m = 0; m < 8; ++m) {
            const float4 xv = xb[m * CH];    // LDS.128, conflict-free
            const u64 xb0 = pack2(xv.x, xv.x);
            const u64 xb1 = pack2(xv.y, xv.y);
            const u64 xb2 = pack2(xv.z, xv.z);
            const u64 xb3 = pack2(xv.w, xv.w);
            #pragma unroll
            for (int rp = 0; rp < 4; ++rp) {
                fma2(acc[m][rp], xb0, bp[2 * rp].x);
                fma2(acc[m][rp], xb1, bp[2 * rp].y);
                fma2(acc[m][rp], xb2, bp[2 * rp + 1].x);
                fma2(acc[m][rp], xb3, bp[2 * rp + 1].y);
            }
        }

        __syncthreads();                     // all done reading buf
        if (s + 2 < NSTG) issue(s + 2, buf);
        else asm volatile("cp.async.commit_group;" ::: "memory"); // keep counts uniform
    }

    // -------- reduce: lanes -> part_s, then k-quarters -> t --------
    #pragma unroll
    for (int sh = 16; sh; sh >>= 1) {
        #pragma unroll
        for (int m = 0; m < 8; ++m)
            #pragma unroll
            for (int rp = 0; rp < 4; ++rp)
                acc[m][rp] = add2(acc[m][rp],
                                  __shfl_xor_sync(0xFFFFFFFFu, acc[m][rp], sh));
    }
    if (lane == 0) {
        #pragma unroll
        for (int m = 0; m < 8; ++m)
            #pragma unroll
            for (int rp = 0; rp < 4; ++rp)
                part_s[kq][rg * 8 + m][rp] = acc[m][rp];
    }
    __syncthreads();

    if (tid < 64) {
        const int row = tid >> 2;
        const int rp  = tid & 3;
        const u64 sum = add2(add2(part_s[0][row][rp], part_s[1][row][rp]),
                             add2(part_s[2][row][rp], part_s[3][row][rp]));
        const float2 f = unpack2(sum);
        const float tA = 2.0f * f.x;         // fold SCALING
        const float tB = 2.0f * f.y;
        t2_s[row][2 * rp + 0] = pack2(tA, tA);
        t2_s[row][2 * rp + 1] = pack2(tB, tB);
    }
    __syncthreads();

    // -------- Phase 2: out = t @ A (R4-proven epilogue) --------
    #pragma unroll
    for (int j = 0; j < 4; ++j) {
        const int p = tid + j * TPB;                 // out f4 col (0..1023)
        u64 alo[RANK], ahi[RANK];
        #pragma unroll
        for (int r = 0; r < RANK; ++r) {
            const float4 a = A4[r * ND4 + p];
            alo[r] = pack2(a.x, a.y);
            ahi[r] = pack2(a.z, a.w);
        }

        #pragma unroll 4
        for (int m = 0; m < ROWS; ++m) {
            const ulonglong2* __restrict__ tp2 = (const ulonglong2*)t2_s[m];
            const ulonglong2 t01 = tp2[0];
            const ulonglong2 t23 = tp2[1];
            const ulonglong2 t45 = tp2[2];
            const ulonglong2 t67 = tp2[3];

            u64 olo = 0ull, ohi = 0ull;
            fma2(olo, t01.x, alo[0]);  fma2(ohi, t01.x, ahi[0]);
            fma2(olo, t01.y, alo[1]);  fma2(ohi, t01.y, ahi[1]);
            fma2(olo, t23.x, alo[2]);  fma2(ohi, t23.x, ahi[2]);
            fma2(olo, t23.y, alo[3]);  fma2(ohi, t23.y, ahi[3]);
            fma2(olo, t45.x, alo[4]);  fma2(ohi, t45.x, ahi[4]);
            fma2(olo, t45.y, alo[5]);  fma2(ohi, t45.y, ahi[5]);
            fma2(olo, t67.x, alo[6]);  fma2(ohi, t67.x, ahi[6]);
            fma2(olo, t67.y, alo[7]);  fma2(ohi, t67.y, ahi[7]);

            const float2 f0 = unpack2(olo);
            const float2 f1 = unpack2(ohi);
            __stcs(&out4[(row0 + m) * ND4 + p],
                   make_float4(f0.x, f0.y, f1.x, f1.y));
        }
    }
}

extern "C" void kernel_launch(void* const* d_in, const int* in_sizes, int n_in,
                              void* d_out, int out_size)
{
    const float* x = (const float*)d_in[0];   // [4,4096,4096]
    const float* A = (const float*)d_in[1];   // [8,4096]
    const float* B = (const float*)d_in[2];   // [4096,8]
    float* out = (float*)d_out;               // [4,4096,4096] fp32

    const int smem = 2 * ROWS * CH * sizeof(float4);   // 64 KB dynamic
    static int configured = 0;
    cudaFuncSetAttribute(lora_v10_kernel,
                         cudaFuncAttributeMaxDynamicSharedMemorySize, smem);
    (void)configured;

    pack_BX_kernel<<<(4 * KDIM) / TPB, TPB>>>(B);

    const int total_rows = 4 * 4096;          // 16384
    lora_v10_kernel<<<total_rows / ROWS, TPB, smem>>>(x, A, out);  // grid 1024
}

// round 11
// speedup vs baseline: 1.1419x; 1.1062x over previous
#include <cuda_runtime.h>

#define TPB    256
#define KDIM   4096
#define KD4    1024
#define ND4    1024
#define RANK   8
#define TROWS  16               // rows per tile
#define NT     1024             // 16384 / TROWS
#define GRID   296              // ~2 CTAs per SM, persistent

typedef unsigned long long u64;

// Interleaved pack of B for 4-line coalesced LDG.128 (verified R7/R8):
// for 32-wide p-block b, 8 segments of 64 u64; seg sub (= rp*2+pr) holds at
// lane*2+j the pair {B[k][2rp],B[k][2rp+1]} for k = 4*(b*32+lane)+2*pr+j.
__device__ u64 BX_g[4 * KDIM];   // 128 KB, L1/L2 resident

__global__ void pack_BX_kernel(const float* __restrict__ B)
{
    const int o = blockIdx.x * blockDim.x + threadIdx.x;  // 0..16383
    const int b    = o >> 9;
    const int r    = o & 511;
    const int sub  = r >> 6;
    const int lane = (r & 63) >> 1;
    const int j    = r & 1;
    const int rp   = sub >> 1;
    const int pr   = sub & 1;
    const int k    = 4 * (b * 32 + lane) + 2 * pr + j;
    BX_g[o] = ((const u64*)B)[k * 4 + rp];
}

__device__ __forceinline__ u64 pack2(float lo, float hi) {
    u64 d; asm("mov.b64 %0, {%1,%2};" : "=l"(d) : "f"(lo), "f"(hi)); return d;
}
__device__ __forceinline__ void fma2(u64 &d, u64 a, u64 b) {
    asm("fma.rn.f32x2 %0, %1, %2, %0;" : "+l"(d) : "l"(a), "l"(b));
}
__device__ __forceinline__ u64 add2(u64 a, u64 b) {
    u64 d; asm("add.rn.f32x2 %0, %1, %2;" : "=l"(d) : "l"(a), "l"(b)); return d;
}
__device__ __forceinline__ float2 unpack2(u64 v) {
    float2 f; asm("mov.b64 {%0,%1}, %2;" : "=f"(f.x), "=f"(f.y) : "l"(v)); return f;
}

// Persistent fused kernel: each CTA strides over 16-row tiles.
// Per tile: phase 1 (warp = 8 rows x k-quarter, R4/R8 engine), phase 2 (R4 epilogue).
__global__ __launch_bounds__(TPB, 2)
void lora_v11_kernel(const float* __restrict__ x,
                     const float* __restrict__ A,
                     float* __restrict__ out)
{
    __shared__ u64 part_s[4][TROWS][4];   // [kq][row][rp]
    __shared__ u64 t2_s[TROWS][RANK];     // {t,t} broadcast pairs

    const int tid  = threadIdx.x;
    const int lane = tid & 31;
    const int warp = tid >> 5;
    const int rg   = warp & 1;            // row half (8 rows)
    const int kq   = warp >> 1;           // k quarter

    const float4* __restrict__ x4 = (const float4*)x;
    const float4* __restrict__ A4 = (const float4*)A;
    float4* __restrict__ out4 = (float4*)out;

    for (int t = blockIdx.x; t < NT; t += GRID) {
        const size_t row0 = (size_t)t * TROWS;

        // ---------------- Phase 1: t = 2 * x_tile @ B ----------------
        {
            const float4* __restrict__ xr = x4 + (row0 + rg * 8) * KD4;

            u64 acc[8][4];
            #pragma unroll
            for (int m = 0; m < 8; ++m)
                #pragma unroll
                for (int rp = 0; rp < 4; ++rp) acc[m][rp] = 0ull;

            #pragma unroll 1
            for (int i = 0; i < 8; ++i) {
                const int p = kq * 256 + i * 32 + lane;    // float4-k index
                const int b = kq * 8 + i;                  // 32-p block

                const ulonglong2* __restrict__ bx =
                    (const ulonglong2*)BX_g + (size_t)b * 256 + lane;
                ulonglong2 bp[8];
                #pragma unroll
                for (int sub = 0; sub < 8; ++sub)
                    bp[sub] = bx[sub * 32];

                #pragma unroll
                for (int h = 0; h < 2; ++h) {
                    float4 xv[4];
                    #pragma unroll
                    for (int q = 0; q < 4; ++q)
                        xv[q] = __ldcs(xr + (h * 4 + q) * KD4 + p);

                    #pragma unroll
                    for (int q = 0; q < 4; ++q) {
                        const int m = h * 4 + q;
                        const u64 xb0 = pack2(xv[q].x, xv[q].x);
                        const u64 xb1 = pack2(xv[q].y, xv[q].y);
                        const u64 xb2 = pack2(xv[q].z, xv[q].z);
                        const u64 xb3 = pack2(xv[q].w, xv[q].w);
                        #pragma unroll
                        for (int rp = 0; rp < 4; ++rp) {
                            fma2(acc[m][rp], xb0, bp[2 * rp].x);
                            fma2(acc[m][rp], xb1, bp[2 * rp].y);
                            fma2(acc[m][rp], xb2, bp[2 * rp + 1].x);
                            fma2(acc[m][rp], xb3, bp[2 * rp + 1].y);
                        }
                    }
                }
            }

            #pragma unroll
            for (int sh = 16; sh; sh >>= 1) {
                #pragma unroll
                for (int m = 0; m < 8; ++m)
                    #pragma unroll
                    for (int rp = 0; rp < 4; ++rp)
                        acc[m][rp] = add2(acc[m][rp],
                            __shfl_xor_sync(0xFFFFFFFFu, acc[m][rp], sh));
            }
            if (lane == 0) {
                #pragma unroll
                for (int m = 0; m < 8; ++m)
                    #pragma unroll
                    for (int rp = 0; rp < 4; ++rp)
                        part_s[kq][rg * 8 + m][rp] = acc[m][rp];
            }
        }
        __syncthreads();   // part_s ready; also: everyone done with prev tile's t2_s

        if (tid < 64) {
            const int row = tid >> 2;
            const int rp  = tid & 3;
            const u64 sum = add2(add2(part_s[0][row][rp], part_s[1][row][rp]),
                                 add2(part_s[2][row][rp], part_s[3][row][rp]));
            const float2 f = unpack2(sum);
            const float tA = 2.0f * f.x;     // fold SCALING
            const float tB = 2.0f * f.y;
            t2_s[row][2 * rp + 0] = pack2(tA, tA);
            t2_s[row][2 * rp + 1] = pack2(tB, tB);
        }
        __syncthreads();   // t2_s ready

        // ---------------- Phase 2: out_tile = t @ A ----------------
        #pragma unroll
        for (int j = 0; j < 4; ++j) {
            const int p = tid + j * TPB;                 // out f4 col (0..1023)
            u64 alo[RANK], ahi[RANK];
            #pragma unroll
            for (int r = 0; r < RANK; ++r) {
                const float4 a = A4[r * ND4 + p];        // L1/L2 hit
                alo[r] = pack2(a.x, a.y);
                ahi[r] = pack2(a.z, a.w);
            }

            #pragma unroll 4
            for (int m = 0; m < TROWS; ++m) {
                const ulonglong2* __restrict__ tp2 = (const ulonglong2*)t2_s[m];
                const ulonglong2 t01 = tp2[0];
                const ulonglong2 t23 = tp2[1];
                const ulonglong2 t45 = tp2[2];
                const ulonglong2 t67 = tp2[3];

                u64 olo = 0ull, ohi = 0ull;
                fma2(olo, t01.x, alo[0]);  fma2(ohi, t01.x, ahi[0]);
                fma2(olo, t01.y, alo[1]);  fma2(ohi, t01.y, ahi[1]);
                fma2(olo, t23.x, alo[2]);  fma2(ohi, t23.x, ahi[2]);
                fma2(olo, t23.y, alo[3]);  fma2(ohi, t23.y, ahi[3]);
                fma2(olo, t45.x, alo[4]);  fma2(ohi, t45.x, ahi[4]);
                fma2(olo, t45.y, alo[5]);  fma2(ohi, t45.y, ahi[5]);
                fma2(olo, t67.x, alo[6]);  fma2(ohi, t67.x, ahi[6]);
                fma2(olo, t67.y, alo[7]);  fma2(ohi, t67.y, ahi[7]);

                const float2 f0 = unpack2(olo);
                const float2 f1 = unpack2(ohi);
                __stcs(&out4[(row0 + m) * ND4 + p],
                       make_float4(f0.x, f0.y, f1.x, f1.y));
            }
        }
        // no extra sync needed: next tile's part_s/t2_s writes are gated by
        // the post-phase-1 __syncthreads, which each thread reaches only
        // after finishing this phase 2.
    }
}

extern "C" void kernel_launch(void* const* d_in, const int* in_sizes, int n_in,
                              void* d_out, int out_size)
{
    const float* x = (const float*)d_in[0];   // [4,4096,4096]
    const float* A = (const float*)d_in[1];   // [8,4096]
    const float* B = (const float*)d_in[2];   // [4096,8]
    float* out = (float*)d_out;               // [4,4096,4096] fp32

    pack_BX_kernel<<<(4 * KDIM) / TPB, TPB>>>(B);
    lora_v11_kernel<<<GRID, TPB>>>(x, A, out);
}